// round 15
// baseline (speedup 1.0000x reference)
#include <cuda_runtime.h>
#include <cstdint>
#include <math.h>

// Fixed shapes: x = (64, 256, 4096) fp32 -> out (64, 256, 816)
#define SEQ      4096
#define MIN_W    20
#define STRIDE   5
#define OUT_LEN  816            // (4096-20)/5 + 1
#define WPT      8              // windows per thread
#define GROUPS   102            // 816 / 8 groups per row
#define EPS      1e-8f
#define NTHREADS 128

// Exact XLA GPU warp-shuffle reduction tree for the 20-element window sum
// (lanes 20..31 carry identity 0; shfl-down 16,8,4,2,1). Bitwise-pinned:
// every add is a single rn FADD, no reassociation, no FMA. The MEAN must be
// bitwise-matched to the reference: global L2 rel_err is dominated by
// near-zero-mean windows where cv = std/(mean+eps) ~ 1e7.
__device__ __forceinline__ float xla_tree20(const float* __restrict__ v)
{
    float c0 = __fadd_rn(__fadd_rn(v[0], v[16]), v[8]);
    float c1 = __fadd_rn(__fadd_rn(v[1], v[17]), v[9]);
    float c2 = __fadd_rn(__fadd_rn(v[2], v[18]), v[10]);
    float c3 = __fadd_rn(__fadd_rn(v[3], v[19]), v[11]);
    float c4 = __fadd_rn(v[4], v[12]);
    float c5 = __fadd_rn(v[5], v[13]);
    float c6 = __fadd_rn(v[6], v[14]);
    float c7 = __fadd_rn(v[7], v[15]);
    float d0 = __fadd_rn(c0, c4);
    float d1 = __fadd_rn(c1, c5);
    float d2 = __fadd_rn(c2, c6);
    float d3 = __fadd_rn(c3, c7);
    return __fadd_rn(__fadd_rn(d0, d2), __fadd_rn(d1, d3));
}

__device__ __forceinline__ float sqrt_approx(float a)
{
    float r;
    asm("sqrt.approx.f32 %0, %1;" : "=f"(r) : "f"(a));
    return r;
}

// Each thread: 8 consecutive windows of one row.
//   group loc in [0,102): windows 8*loc..8*loc+7,
//   elements [40*loc, 40*loc+56) = exactly 14 aligned float4 loads
//   (160*loc bytes is 16B-aligned; group 101 ends exactly at element 4096).
// 56 loaded elements serve 8 windows: L1-level read amplification drops
// from 1.8x (4 windows / 36 elems) to 1.4x, and per-window instruction
// overhead (loads, chunk FFMAs, stores) drops ~25%.
__global__ __launch_bounds__(NTHREADS) void tscv_kernel(
    const float* __restrict__ x,
    float*       __restrict__ out)
{
    const int g   = blockIdx.x * NTHREADS + threadIdx.x;
    const int row = g / GROUPS;
    const int loc = g - row * GROUPS;

    const float4* __restrict__ src4 = reinterpret_cast<const float4*>(
        x + (size_t)row * SEQ + (size_t)(WPT * STRIDE) * loc);

    float v[56];
    #pragma unroll
    for (int i = 0; i < 14; ++i) {
        const float4 t = src4[i];
        v[4 * i + 0] = t.x;
        v[4 * i + 1] = t.y;
        v[4 * i + 2] = t.z;
        v[4 * i + 3] = t.w;
    }

    // Shared chunk sums of squares: cs[i] = sum v[5i..5i+4]^2 (i = 0..10).
    // Window j's sumsq = chunks j..j+3. std only needs ~1e-5 relative
    // accuracy; the error budget is carried by the bitwise-exact mean.
    float cs[11];
    #pragma unroll
    for (int i = 0; i < 11; ++i) {
        const float* c = v + 5 * i;
        float a = __fmul_rn(c[0], c[0]);
        a = __fmaf_rn(c[1], c[1], a);
        a = __fmaf_rn(c[2], c[2], a);
        a = __fmaf_rn(c[3], c[3], a);
        a = __fmaf_rn(c[4], c[4], a);
        cs[i] = a;
    }

    float res[WPT];
    #pragma unroll
    for (int j = 0; j < WPT; ++j) {
        const float* w = v + STRIDE * j;

        // Exact mean: pinned-order tree sum, then recip-mult.
        const float s    = xla_tree20(w);
        const float mean = __fmul_rn(s, 0.05f);

        // sumsq from shared chunks; sum((x-m)^2) = sumsq - 2ms + 20m^2.
        const float sumsq = __fadd_rn(__fadd_rn(cs[j],     cs[j + 1]),
                                      __fadd_rn(cs[j + 2], cs[j + 3]));
        const float ss  = __fmaf_rn(mean,
                                    __fmaf_rn(20.0f, mean, -2.0f * s),
                                    sumsq);
        const float var = fmaxf(ss, 0.0f) * (float)(1.0 / 19.0);
        const float sd  = sqrt_approx(var);

        float cv = __fdividef(sd, __fadd_rn(mean, EPS));
        res[j] = (cv != cv) ? 0.0f : cv;   // NaN -> 0 (matches jnp.where)
    }

    // 8 consecutive outputs -> two aligned 16B stores.
    float* op = out + (size_t)row * OUT_LEN + WPT * loc;
    float4 o0, o1;
    o0.x = res[0]; o0.y = res[1]; o0.z = res[2]; o0.w = res[3];
    o1.x = res[4]; o1.y = res[5]; o1.z = res[6]; o1.w = res[7];
    reinterpret_cast<float4*>(op)[0] = o0;
    reinterpret_cast<float4*>(op)[1] = o1;
}

extern "C" void kernel_launch(void* const* d_in, const int* in_sizes, int n_in,
                              void* d_out, int out_size)
{
    const float* x = (const float*)d_in[0];
    float* out = (float*)d_out;

    // 16384 rows * 102 groups = 1,671,168 threads = 13056 CTAs of 128.
    const int n_rows = in_sizes[0] / SEQ;
    const int n_ctas = (n_rows * GROUPS) / NTHREADS;
    tscv_kernel<<<n_ctas, NTHREADS>>>(x, out);
}